// round 4
// baseline (speedup 1.0000x reference)
#include <cuda_runtime.h>
#include <cuda_fp16.h>
#include <cstdint>

// Problem dims
#define NTOK   32768
#define HIDDEN 1024
#define INTER  768

// ---------------- scratch (static device memory; no allocs) ----------------
static __device__ __align__(128) __half g_Xh[(size_t)NTOK * HIDDEN];   // 64 MB
static __device__ __align__(128) __half g_Wg[INTER * HIDDEN];          // 1.5 MB
static __device__ __align__(128) __half g_Wu[INTER * HIDDEN];          // 1.5 MB
static __device__ __align__(128) __half g_Wd[HIDDEN * INTER];          // 1.5 MB
static __device__ __align__(128) __half g_H [(size_t)NTOK * INTER];    // 48 MB

// ---------------- helpers ----------------
__device__ __forceinline__ uint32_t smem_u32(const void* p) {
    uint32_t a;
    asm("{ .reg .u64 t; cvta.to.shared.u64 t, %1; cvt.u32.u64 %0, t; }" : "=r"(a) : "l"(p));
    return a;
}

#define SW128(o) ((uint32_t)(o) ^ ((((uint32_t)(o)) >> 3) & 0x70))

__device__ __forceinline__ void cp_async16(uint32_t saddr, const void* gaddr) {
    asm volatile("cp.async.cg.shared.global [%0], [%1], 16;\n" :: "r"(saddr), "l"(gaddr));
}
__device__ __forceinline__ void cp_commit() { asm volatile("cp.async.commit_group;\n" ::: "memory"); }
__device__ __forceinline__ void cp_wait1()  { asm volatile("cp.async.wait_group 1;\n" ::: "memory"); }

__device__ __forceinline__ void ldm_x4(uint32_t* r, uint32_t saddr) {
    asm volatile("ldmatrix.sync.aligned.m8n8.x4.shared.b16 {%0,%1,%2,%3}, [%4];"
                 : "=r"(r[0]), "=r"(r[1]), "=r"(r[2]), "=r"(r[3]) : "r"(saddr));
}

__device__ __forceinline__ void mma16816(float* c, const uint32_t* a, uint32_t b0, uint32_t b1) {
    asm volatile("mma.sync.aligned.m16n8k16.row.col.f32.f16.f16.f32 "
                 "{%0,%1,%2,%3}, {%4,%5,%6,%7}, {%8,%9}, {%0,%1,%2,%3};"
                 : "+f"(c[0]), "+f"(c[1]), "+f"(c[2]), "+f"(c[3])
                 : "r"(a[0]), "r"(a[1]), "r"(a[2]), "r"(a[3]), "r"(b0), "r"(b1));
}

// ---------------- conversion kernels ----------------
__global__ void k_conv_x(const float* __restrict__ X) {
    size_t n4 = (size_t)NTOK * HIDDEN / 4;
    size_t stride = (size_t)gridDim.x * blockDim.x;
    __half2* dst = reinterpret_cast<__half2*>(g_Xh);
    for (size_t i = (size_t)blockIdx.x * blockDim.x + threadIdx.x; i < n4; i += stride) {
        float4 v = reinterpret_cast<const float4*>(X)[i];
        dst[2 * i + 0] = __floats2half2_rn(v.x, v.y);
        dst[2 * i + 1] = __floats2half2_rn(v.z, v.w);
    }
}

__global__ void k_conv_w(const float* __restrict__ G, const float* __restrict__ U,
                         const float* __restrict__ D, const int* __restrict__ E) {
    int e = E[0];
    size_t base = (size_t)e * (INTER * HIDDEN);
    size_t n4 = (size_t)(INTER * HIDDEN) / 4;
    size_t stride = (size_t)gridDim.x * blockDim.x;
    __half2* wg = reinterpret_cast<__half2*>(g_Wg);
    __half2* wu = reinterpret_cast<__half2*>(g_Wu);
    __half2* wd = reinterpret_cast<__half2*>(g_Wd);
    for (size_t i = (size_t)blockIdx.x * blockDim.x + threadIdx.x; i < n4; i += stride) {
        float4 g = reinterpret_cast<const float4*>(G + base)[i];
        float4 u = reinterpret_cast<const float4*>(U + base)[i];
        float4 d = reinterpret_cast<const float4*>(D + base)[i];
        wg[2 * i + 0] = __floats2half2_rn(g.x, g.y);
        wg[2 * i + 1] = __floats2half2_rn(g.z, g.w);
        wu[2 * i + 0] = __floats2half2_rn(u.x, u.y);
        wu[2 * i + 1] = __floats2half2_rn(u.z, u.w);
        wd[2 * i + 0] = __floats2half2_rn(d.x, d.y);
        wd[2 * i + 1] = __floats2half2_rn(d.z, d.w);
    }
}

// ======================== fused gate+up GEMM ========================
// C_g = X @ Wg^T, C_u = X @ Wu^T on the same (m,n) tile; H = SiLU(C_g)*C_u (fp16)
// BM=128, BN=64 (INTER), BK=64. 256 thr = 8 warps (4 x 2). 3-stage cp.async.
#define GU_BM 128
#define GU_BN 64
#define GU_BK 64
#define GU_STAGE (GU_BM * GU_BK * 2 + 2 * GU_BN * GU_BK * 2)   // A 16K + Bg 8K + Bu 8K = 32768
#define GU_SMEM  (3 * GU_STAGE)                                 // 98304

__device__ __forceinline__ void gu_load_stage(uint32_t sstage, int m0, int n0, int k0, int tid) {
    // A: 128x64 fp16 = 1024 16B-chunks
#pragma unroll
    for (int i = 0; i < 4; i++) {
        int idx = tid + i * 256;
        int r = idx >> 3, c = idx & 7;
        cp_async16(sstage + SW128(r * 128 + c * 16),
                   g_Xh + (size_t)(m0 + r) * HIDDEN + k0 + c * 8);
    }
    // Bg, Bu: 64x64 fp16 = 512 chunks each
#pragma unroll
    for (int i = 0; i < 2; i++) {
        int idx = tid + i * 256;
        int r = idx >> 3, c = idx & 7;
        uint32_t off = SW128(r * 128 + c * 16);
        cp_async16(sstage + GU_BM * GU_BK * 2 + off,
                   g_Wg + (size_t)(n0 + r) * HIDDEN + k0 + c * 8);
        cp_async16(sstage + GU_BM * GU_BK * 2 + GU_BN * GU_BK * 2 + off,
                   g_Wu + (size_t)(n0 + r) * HIDDEN + k0 + c * 8);
    }
}

__global__ void __launch_bounds__(256, 2) k_gateup() {
    extern __shared__ __align__(1024) char smem[];
    uint32_t su = smem_u32(smem);
    int tid = threadIdx.x, lane = tid & 31, wid = tid >> 5;
    int warp_m = wid >> 1, warp_n = wid & 1;
    int m0 = blockIdx.x * GU_BM;
    int n0 = blockIdx.y * GU_BN;

    // raw (pre-swizzle) ldmatrix offsets: row*128 + hi16*16 ; k adds ks*32
    int lrow = lane & 15, lhi = lane >> 4;
    uint32_t rawA[2], rawB[2];
#pragma unroll
    for (int mt = 0; mt < 2; mt++)
        rawA[mt] = (uint32_t)((warp_m * 32 + mt * 16 + lrow) * 128 + lhi * 16);
#pragma unroll
    for (int p = 0; p < 2; p++)
        rawB[p] = (uint32_t)((warp_n * 32 + p * 16 + lrow) * 128 + lhi * 16);

    float cg[2][4][4], cu[2][4][4];
#pragma unroll
    for (int mt = 0; mt < 2; mt++)
#pragma unroll
        for (int nt = 0; nt < 4; nt++)
#pragma unroll
            for (int i = 0; i < 4; i++) { cg[mt][nt][i] = 0.f; cu[mt][nt][i] = 0.f; }

    const int NK = HIDDEN / GU_BK;   // 16
    // prologue: stages 0,1
    gu_load_stage(su + 0 * GU_STAGE, m0, n0, 0 * GU_BK, tid); cp_commit();
    gu_load_stage(su + 1 * GU_STAGE, m0, n0, 1 * GU_BK, tid); cp_commit();

    for (int k = 0; k < NK; k++) {
        cp_wait1();
        __syncthreads();
        int kp = k + 2;
        if (kp < NK) gu_load_stage(su + (kp % 3) * GU_STAGE, m0, n0, kp * GU_BK, tid);
        cp_commit();

        uint32_t sb = su + (k % 3) * GU_STAGE;
        uint32_t sbg = sb + GU_BM * GU_BK * 2;
        uint32_t sbu = sbg + GU_BN * GU_BK * 2;
#pragma unroll
        for (int ks = 0; ks < 4; ks++) {
            uint32_t a[2][4], bg[2][4], bu[2][4];
#pragma unroll
            for (int mt = 0; mt < 2; mt++) {
                uint32_t off = rawA[mt] + ks * 32; off = SW128(off);
                ldm_x4(a[mt], sb + off);
            }
#pragma unroll
            for (int p = 0; p < 2; p++) {
                uint32_t off = rawB[p] + ks * 32; off = SW128(off);
                ldm_x4(bg[p], sbg + off);
                ldm_x4(bu[p], sbu + off);
            }
#pragma unroll
            for (int mt = 0; mt < 2; mt++)
#pragma unroll
                for (int nt = 0; nt < 4; nt++) {
                    int p = nt >> 1, hi = nt & 1;
                    mma16816(cg[mt][nt], a[mt], bg[p][hi], bg[p][2 + hi]);
                    mma16816(cu[mt][nt], a[mt], bu[p][hi], bu[p][2 + hi]);
                }
        }
    }

    // epilogue: SiLU(gate)*up -> fp16 -> g_H
    int r0 = m0 + warp_m * 32 + (lane >> 2);
    int c0 = n0 + warp_n * 32 + (lane & 3) * 2;
#pragma unroll
    for (int mt = 0; mt < 2; mt++)
#pragma unroll
        for (int nt = 0; nt < 4; nt++) {
            int col = c0 + nt * 8;
#pragma unroll
            for (int half = 0; half < 2; half++) {
                int r = r0 + mt * 16 + half * 8;
                float g0 = cg[mt][nt][2 * half + 0], g1 = cg[mt][nt][2 * half + 1];
                float u0 = cu[mt][nt][2 * half + 0], u1 = cu[mt][nt][2 * half + 1];
                float h0 = (g0 / (1.0f + __expf(-g0))) * u0;
                float h1 = (g1 / (1.0f + __expf(-g1))) * u1;
                __half2 hh = __floats2half2_rn(h0, h1);
                *reinterpret_cast<__half2*>(g_H + (size_t)r * INTER + col) = hh;
            }
        }
}

// ======================== down GEMM ========================
// out = H @ Wd^T : [NTOK, HIDDEN] fp32. BM=128, BN=128, BK=64. warps 2x4.
#define DN_BM 128
#define DN_BN 128
#define DN_BK 64
#define DN_STAGE (DN_BM * DN_BK * 2 + DN_BN * DN_BK * 2)   // 16K + 16K = 32768
#define DN_SMEM  (3 * DN_STAGE)                             // 98304

__device__ __forceinline__ void dn_load_stage(uint32_t sstage, int m0, int n0, int k0, int tid) {
#pragma unroll
    for (int i = 0; i < 4; i++) {
        int idx = tid + i * 256;
        int r = idx >> 3, c = idx & 7;
        uint32_t off = SW128(r * 128 + c * 16);
        cp_async16(sstage + off, g_H + (size_t)(m0 + r) * INTER + k0 + c * 8);
        cp_async16(sstage + DN_BM * DN_BK * 2 + off,
                   g_Wd + (size_t)(n0 + r) * INTER + k0 + c * 8);
    }
}

__global__ void __launch_bounds__(256, 2) k_down(float* __restrict__ out) {
    extern __shared__ __align__(1024) char smem[];
    uint32_t su = smem_u32(smem);
    int tid = threadIdx.x, lane = tid & 31, wid = tid >> 5;
    int warp_m = wid >> 2, warp_n = wid & 3;   // 2 x 4 -> warp tile 64 x 32
    int m0 = blockIdx.x * DN_BM;
    int n0 = blockIdx.y * DN_BN;

    int lrow = lane & 15, lhi = lane >> 4;
    uint32_t rawA[4], rawB[2];
#pragma unroll
    for (int mt = 0; mt < 4; mt++)
        rawA[mt] = (uint32_t)((warp_m * 64 + mt * 16 + lrow) * 128 + lhi * 16);
#pragma unroll
    for (int p = 0; p < 2; p++)
        rawB[p] = (uint32_t)((warp_n * 32 + p * 16 + lrow) * 128 + lhi * 16);

    float acc[4][4][4];
#pragma unroll
    for (int mt = 0; mt < 4; mt++)
#pragma unroll
        for (int nt = 0; nt < 4; nt++)
#pragma unroll
            for (int i = 0; i < 4; i++) acc[mt][nt][i] = 0.f;

    const int NK = INTER / DN_BK;    // 12
    dn_load_stage(su + 0 * DN_STAGE, m0, n0, 0 * DN_BK, tid); cp_commit();
    dn_load_stage(su + 1 * DN_STAGE, m0, n0, 1 * DN_BK, tid); cp_commit();

    for (int k = 0; k < NK; k++) {
        cp_wait1();
        __syncthreads();
        int kp = k + 2;
        if (kp < NK) dn_load_stage(su + (kp % 3) * DN_STAGE, m0, n0, kp * DN_BK, tid);
        cp_commit();

        uint32_t sa = su + (k % 3) * DN_STAGE;
        uint32_t sbb = sa + DN_BM * DN_BK * 2;
#pragma unroll
        for (int ks = 0; ks < 4; ks++) {
            uint32_t b[2][4];
#pragma unroll
            for (int p = 0; p < 2; p++) {
                uint32_t off = rawB[p] + ks * 32; off = SW128(off);
                ldm_x4(b[p], sbb + off);
            }
#pragma unroll
            for (int mt = 0; mt < 4; mt++) {
                uint32_t a[4];
                uint32_t off = rawA[mt] + ks * 32; off = SW128(off);
                ldm_x4(a, sa + off);
#pragma unroll
                for (int nt = 0; nt < 4; nt++) {
                    int p = nt >> 1, hi = nt & 1;
                    mma16816(acc[mt][nt], a, b[p][hi], b[p][2 + hi]);
                }
            }
        }
    }

    // epilogue: fp32 out
    int r0 = m0 + warp_m * 64 + (lane >> 2);
    int c0 = n0 + warp_n * 32 + (lane & 3) * 2;
#pragma unroll
    for (int mt = 0; mt < 4; mt++)
#pragma unroll
        for (int nt = 0; nt < 4; nt++) {
            int col = c0 + nt * 8;
            int r = r0 + mt * 16;
            float2 v0 = make_float2(acc[mt][nt][0], acc[mt][nt][1]);
            float2 v1 = make_float2(acc[mt][nt][2], acc[mt][nt][3]);
            *reinterpret_cast<float2*>(out + (size_t)r * HIDDEN + col) = v0;
            *reinterpret_cast<float2*>(out + (size_t)(r + 8) * HIDDEN + col) = v1;
        }
}

// ---------------- launch ----------------
extern "C" void kernel_launch(void* const* d_in, const int* in_sizes, int n_in,
                              void* d_out, int out_size) {
    const float* X = (const float*)d_in[0];
    const float* G = (const float*)d_in[1];
    const float* U = (const float*)d_in[2];
    const float* D = (const float*)d_in[3];
    const int*   E = (const int*)d_in[4];
    float* out = (float*)d_out;

    cudaFuncSetAttribute(k_gateup, cudaFuncAttributeMaxDynamicSharedMemorySize, GU_SMEM);
    cudaFuncSetAttribute(k_down,   cudaFuncAttributeMaxDynamicSharedMemorySize, DN_SMEM);

    k_conv_w<<<384, 512>>>(G, U, D, E);
    k_conv_x<<<4096, 512>>>(X);
    k_gateup<<<dim3(NTOK / GU_BM, INTER / GU_BN), 256, GU_SMEM>>>();
    k_down<<<dim3(NTOK / DN_BM, HIDDEN / DN_BN), 256, DN_SMEM>>>(out);
    (void)in_sizes; (void)n_in; (void)out_size;
}

// round 5
// speedup vs baseline: 1.5122x; 1.5122x over previous
#include <cuda_runtime.h>
#include <cuda_fp16.h>
#include <cstdint>

// Problem dims
#define NTOK   32768
#define HIDDEN 1024
#define INTER  768

// ---------------- scratch (static device memory; no allocs) ----------------
static __device__ __align__(128) __half g_Xh[(size_t)NTOK * HIDDEN];   // 64 MB
static __device__ __align__(128) __half g_Wg[INTER * HIDDEN];          // 1.5 MB
static __device__ __align__(128) __half g_Wu[INTER * HIDDEN];          // 1.5 MB
static __device__ __align__(128) __half g_Wd[HIDDEN * INTER];          // 1.5 MB
static __device__ __align__(128) __half g_H [(size_t)NTOK * INTER];    // 48 MB

// ---------------- helpers ----------------
__device__ __forceinline__ uint32_t smem_u32(const void* p) {
    uint32_t a;
    asm("{ .reg .u64 t; cvta.to.shared.u64 t, %1; cvt.u32.u64 %0, t; }" : "=r"(a) : "l"(p));
    return a;
}

#define SW128(o) ((uint32_t)(o) ^ ((((uint32_t)(o)) >> 3) & 0x70))

__device__ __forceinline__ void cp_async16(uint32_t saddr, const void* gaddr) {
    asm volatile("cp.async.cg.shared.global [%0], [%1], 16;\n" :: "r"(saddr), "l"(gaddr));
}
__device__ __forceinline__ void cp_commit() { asm volatile("cp.async.commit_group;\n" ::: "memory"); }
__device__ __forceinline__ void cp_wait1()  { asm volatile("cp.async.wait_group 1;\n" ::: "memory"); }

__device__ __forceinline__ void ldm_x4(uint32_t* r, uint32_t saddr) {
    asm volatile("ldmatrix.sync.aligned.m8n8.x4.shared.b16 {%0,%1,%2,%3}, [%4];"
                 : "=r"(r[0]), "=r"(r[1]), "=r"(r[2]), "=r"(r[3]) : "r"(saddr));
}

__device__ __forceinline__ void mma16816(float* c, const uint32_t* a, uint32_t b0, uint32_t b1) {
    asm volatile("mma.sync.aligned.m16n8k16.row.col.f32.f16.f16.f32 "
                 "{%0,%1,%2,%3}, {%4,%5,%6,%7}, {%8,%9}, {%0,%1,%2,%3};"
                 : "+f"(c[0]), "+f"(c[1]), "+f"(c[2]), "+f"(c[3])
                 : "r"(a[0]), "r"(a[1]), "r"(a[2]), "r"(a[3]), "r"(b0), "r"(b1));
}

// ---------------- conversion kernels ----------------
__global__ void k_conv_x(const float* __restrict__ X) {
    size_t n4 = (size_t)NTOK * HIDDEN / 4;
    size_t stride = (size_t)gridDim.x * blockDim.x;
    __half2* dst = reinterpret_cast<__half2*>(g_Xh);
    for (size_t i = (size_t)blockIdx.x * blockDim.x + threadIdx.x; i < n4; i += stride) {
        float4 v = reinterpret_cast<const float4*>(X)[i];
        dst[2 * i + 0] = __floats2half2_rn(v.x, v.y);
        dst[2 * i + 1] = __floats2half2_rn(v.z, v.w);
    }
}

__global__ void k_conv_w(const float* __restrict__ G, const float* __restrict__ U,
                         const float* __restrict__ D, const int* __restrict__ E) {
    int e = E[0];
    size_t base = (size_t)e * (INTER * HIDDEN);
    size_t n4 = (size_t)(INTER * HIDDEN) / 4;
    size_t stride = (size_t)gridDim.x * blockDim.x;
    __half2* wg = reinterpret_cast<__half2*>(g_Wg);
    __half2* wu = reinterpret_cast<__half2*>(g_Wu);
    __half2* wd = reinterpret_cast<__half2*>(g_Wd);
    for (size_t i = (size_t)blockIdx.x * blockDim.x + threadIdx.x; i < n4; i += stride) {
        float4 g = reinterpret_cast<const float4*>(G + base)[i];
        float4 u = reinterpret_cast<const float4*>(U + base)[i];
        float4 d = reinterpret_cast<const float4*>(D + base)[i];
        wg[2 * i + 0] = __floats2half2_rn(g.x, g.y);
        wg[2 * i + 1] = __floats2half2_rn(g.z, g.w);
        wu[2 * i + 0] = __floats2half2_rn(u.x, u.y);
        wu[2 * i + 1] = __floats2half2_rn(u.z, u.w);
        wd[2 * i + 0] = __floats2half2_rn(d.x, d.y);
        wd[2 * i + 1] = __floats2half2_rn(d.z, d.w);
    }
}

// ======================== fused gate+up GEMM ========================
// C_g = X @ Wg^T, C_u = X @ Wu^T on the same (m,n) tile; H = SiLU(C_g)*C_u (fp16)
// BM=128, BN=64, BK=64. 256 thr = 8 warps (4 x 2). 3-stage cp.async.
#define GU_BM 128
#define GU_BN 64
#define GU_BK 64
#define GU_STAGE (GU_BM * GU_BK * 2 + 2 * GU_BN * GU_BK * 2)   // 32768
#define GU_SMEM  (3 * GU_STAGE)                                 // 98304

__device__ __forceinline__ void gu_load_stage(uint32_t sstage, int m0, int n0, int k0, int tid) {
#pragma unroll
    for (int i = 0; i < 4; i++) {
        int idx = tid + i * 256;
        int r = idx >> 3, c = idx & 7;
        cp_async16(sstage + SW128(r * 128 + c * 16),
                   g_Xh + (size_t)(m0 + r) * HIDDEN + k0 + c * 8);
    }
#pragma unroll
    for (int i = 0; i < 2; i++) {
        int idx = tid + i * 256;
        int r = idx >> 3, c = idx & 7;
        uint32_t off = SW128(r * 128 + c * 16);
        cp_async16(sstage + GU_BM * GU_BK * 2 + off,
                   g_Wg + (size_t)(n0 + r) * HIDDEN + k0 + c * 8);
        cp_async16(sstage + GU_BM * GU_BK * 2 + GU_BN * GU_BK * 2 + off,
                   g_Wu + (size_t)(n0 + r) * HIDDEN + k0 + c * 8);
    }
}

__global__ void __launch_bounds__(256, 2) k_gateup() {
    extern __shared__ __align__(1024) char smem[];
    uint32_t su = smem_u32(smem);
    int tid = threadIdx.x, lane = tid & 31, wid = tid >> 5;
    int warp_m = wid >> 1, warp_n = wid & 1;
    int m0 = blockIdx.x * GU_BM;
    int n0 = blockIdx.y * GU_BN;

    int lrow = lane & 15, lhi = lane >> 4;
    uint32_t rawA[2], rawB[2];
#pragma unroll
    for (int mt = 0; mt < 2; mt++)
        rawA[mt] = (uint32_t)((warp_m * 32 + mt * 16 + lrow) * 128 + lhi * 16);
#pragma unroll
    for (int p = 0; p < 2; p++)
        rawB[p] = (uint32_t)((warp_n * 32 + p * 16 + lrow) * 128 + lhi * 16);

    float cg[2][4][4], cu[2][4][4];
#pragma unroll
    for (int mt = 0; mt < 2; mt++)
#pragma unroll
        for (int nt = 0; nt < 4; nt++)
#pragma unroll
            for (int i = 0; i < 4; i++) { cg[mt][nt][i] = 0.f; cu[mt][nt][i] = 0.f; }

    const int NK = HIDDEN / GU_BK;   // 16
    gu_load_stage(su + 0 * GU_STAGE, m0, n0, 0 * GU_BK, tid); cp_commit();
    gu_load_stage(su + 1 * GU_STAGE, m0, n0, 1 * GU_BK, tid); cp_commit();

    for (int k = 0; k < NK; k++) {
        cp_wait1();
        __syncthreads();
        int kp = k + 2;
        if (kp < NK) gu_load_stage(su + (kp % 3) * GU_STAGE, m0, n0, kp * GU_BK, tid);
        cp_commit();

        uint32_t sb  = su + (k % 3) * GU_STAGE;
        uint32_t sbg = sb + GU_BM * GU_BK * 2;
        uint32_t sbu = sbg + GU_BN * GU_BK * 2;

        // register-pipelined fragments: a double-buffered per step,
        // bg/bu double-buffered per ks
        uint32_t a[2][4], bg[2][2][4], bu[2][2][4];
#pragma unroll
        for (int p = 0; p < 2; p++) {
            ldm_x4(bg[0][p], sbg + SW128(rawB[p]));
            ldm_x4(bu[0][p], sbu + SW128(rawB[p]));
        }
        ldm_x4(a[0], sb + SW128(rawA[0]));

        // steps s = 0..7 : ks = s>>1, mt = s&1
#pragma unroll
        for (int s = 0; s < 8; s++) {
            int ks = s >> 1, mt = s & 1, kb = ks & 1;
            // prefetch next A fragment
            if (s < 7) {
                int ns = s + 1, nks = ns >> 1, nmt = ns & 1;
                ldm_x4(a[ns & 1], sb + SW128(rawA[nmt] + nks * 32));
            }
            // prefetch next-ks B fragments (at mt==0 step, 2 steps ahead of use)
            if (mt == 0 && ks < 3) {
                int nb = (ks + 1) & 1;
#pragma unroll
                for (int p = 0; p < 2; p++) {
                    ldm_x4(bg[nb][p], sbg + SW128(rawB[p] + (ks + 1) * 32));
                    ldm_x4(bu[nb][p], sbu + SW128(rawB[p] + (ks + 1) * 32));
                }
            }
#pragma unroll
            for (int nt = 0; nt < 4; nt++) {
                int p = nt >> 1, hi = nt & 1;
                mma16816(cg[mt][nt], a[s & 1], bg[kb][p][hi], bg[kb][p][2 + hi]);
                mma16816(cu[mt][nt], a[s & 1], bu[kb][p][hi], bu[kb][p][2 + hi]);
            }
        }
    }

    // epilogue: SiLU(gate)*up -> fp16 -> g_H
    int r0 = m0 + warp_m * 32 + (lane >> 2);
    int c0 = n0 + warp_n * 32 + (lane & 3) * 2;
#pragma unroll
    for (int mt = 0; mt < 2; mt++)
#pragma unroll
        for (int nt = 0; nt < 4; nt++) {
            int col = c0 + nt * 8;
#pragma unroll
            for (int half = 0; half < 2; half++) {
                int r = r0 + mt * 16 + half * 8;
                float g0 = cg[mt][nt][2 * half + 0], g1 = cg[mt][nt][2 * half + 1];
                float u0 = cu[mt][nt][2 * half + 0], u1 = cu[mt][nt][2 * half + 1];
                float h0 = (g0 / (1.0f + __expf(-g0))) * u0;
                float h1 = (g1 / (1.0f + __expf(-g1))) * u1;
                __half2 hh = __floats2half2_rn(h0, h1);
                *reinterpret_cast<__half2*>(g_H + (size_t)r * INTER + col) = hh;
            }
        }
}

// ======================== down GEMM ========================
// out = H @ Wd^T : [NTOK, HIDDEN] fp32. BM=128, BN=128, BK=64. warps 2x4, warp 64x32.
#define DN_BM 128
#define DN_BN 128
#define DN_BK 64
#define DN_STAGE (DN_BM * DN_BK * 2 + DN_BN * DN_BK * 2)   // 32768
#define DN_SMEM  (3 * DN_STAGE)                             // 98304

__device__ __forceinline__ void dn_load_stage(uint32_t sstage, int m0, int n0, int k0, int tid) {
#pragma unroll
    for (int i = 0; i < 4; i++) {
        int idx = tid + i * 256;
        int r = idx >> 3, c = idx & 7;
        uint32_t off = SW128(r * 128 + c * 16);
        cp_async16(sstage + off, g_H + (size_t)(m0 + r) * INTER + k0 + c * 8);
        cp_async16(sstage + DN_BM * DN_BK * 2 + off,
                   g_Wd + (size_t)(n0 + r) * INTER + k0 + c * 8);
    }
}

__global__ void __launch_bounds__(256, 2) k_down(float* __restrict__ out) {
    extern __shared__ __align__(1024) char smem[];
    uint32_t su = smem_u32(smem);
    int tid = threadIdx.x, lane = tid & 31, wid = tid >> 5;
    int warp_m = wid >> 2, warp_n = wid & 3;   // 2 x 4 -> warp tile 64 x 32
    int m0 = blockIdx.x * DN_BM;
    int n0 = blockIdx.y * DN_BN;

    int lrow = lane & 15, lhi = lane >> 4;
    uint32_t rawA[4], rawB[2];
#pragma unroll
    for (int mt = 0; mt < 4; mt++)
        rawA[mt] = (uint32_t)((warp_m * 64 + mt * 16 + lrow) * 128 + lhi * 16);
#pragma unroll
    for (int p = 0; p < 2; p++)
        rawB[p] = (uint32_t)((warp_n * 32 + p * 16 + lrow) * 128 + lhi * 16);

    float acc[4][4][4];
#pragma unroll
    for (int mt = 0; mt < 4; mt++)
#pragma unroll
        for (int nt = 0; nt < 4; nt++)
#pragma unroll
            for (int i = 0; i < 4; i++) acc[mt][nt][i] = 0.f;

    const int NK = INTER / DN_BK;    // 12
    dn_load_stage(su + 0 * DN_STAGE, m0, n0, 0 * DN_BK, tid); cp_commit();
    dn_load_stage(su + 1 * DN_STAGE, m0, n0, 1 * DN_BK, tid); cp_commit();

    for (int k = 0; k < NK; k++) {
        cp_wait1();
        __syncthreads();
        int kp = k + 2;
        if (kp < NK) dn_load_stage(su + (kp % 3) * DN_STAGE, m0, n0, kp * DN_BK, tid);
        cp_commit();

        uint32_t sa  = su + (k % 3) * DN_STAGE;
        uint32_t sbb = sa + DN_BM * DN_BK * 2;

        // register-pipelined fragments
        uint32_t a[2][4], b[2][2][4];
#pragma unroll
        for (int p = 0; p < 2; p++) ldm_x4(b[0][p], sbb + SW128(rawB[p]));
        ldm_x4(a[0], sa + SW128(rawA[0]));

        // steps s = 0..15 : ks = s>>2, mt = s&3
#pragma unroll
        for (int s = 0; s < 16; s++) {
            int ks = s >> 2, mt = s & 3, kb = ks & 1;
            if (s < 15) {
                int ns = s + 1, nks = ns >> 2, nmt = ns & 3;
                ldm_x4(a[ns & 1], sa + SW128(rawA[nmt] + nks * 32));
            }
            if (mt == 0 && ks < 3) {
                int nb = (ks + 1) & 1;
#pragma unroll
                for (int p = 0; p < 2; p++)
                    ldm_x4(b[nb][p], sbb + SW128(rawB[p] + (ks + 1) * 32));
            }
#pragma unroll
            for (int nt = 0; nt < 4; nt++) {
                int p = nt >> 1, hi = nt & 1;
                mma16816(acc[mt][nt], a[s & 1], b[kb][p][hi], b[kb][p][2 + hi]);
            }
        }
    }

    // epilogue: fp32 out
    int r0 = m0 + warp_m * 64 + (lane >> 2);
    int c0 = n0 + warp_n * 32 + (lane & 3) * 2;
#pragma unroll
    for (int mt = 0; mt < 4; mt++)
#pragma unroll
        for (int nt = 0; nt < 4; nt++) {
            int col = c0 + nt * 8;
            int r = r0 + mt * 16;
            float2 v0 = make_float2(acc[mt][nt][0], acc[mt][nt][1]);
            float2 v1 = make_float2(acc[mt][nt][2], acc[mt][nt][3]);
            *reinterpret_cast<float2*>(out + (size_t)r * HIDDEN + col) = v0;
            *reinterpret_cast<float2*>(out + (size_t)(r + 8) * HIDDEN + col) = v1;
        }
}

// ---------------- launch ----------------
extern "C" void kernel_launch(void* const* d_in, const int* in_sizes, int n_in,
                              void* d_out, int out_size) {
    const float* X = (const float*)d_in[0];
    const float* G = (const float*)d_in[1];
    const float* U = (const float*)d_in[2];
    const float* D = (const float*)d_in[3];
    const int*   E = (const int*)d_in[4];
    float* out = (float*)d_out;

    cudaFuncSetAttribute(k_gateup, cudaFuncAttributeMaxDynamicSharedMemorySize, GU_SMEM);
    cudaFuncSetAttribute(k_down,   cudaFuncAttributeMaxDynamicSharedMemorySize, DN_SMEM);

    k_conv_w<<<384, 512>>>(G, U, D, E);
    k_conv_x<<<4096, 512>>>(X);
    k_gateup<<<dim3(NTOK / GU_BM, INTER / GU_BN), 256, GU_SMEM>>>();
    k_down<<<dim3(NTOK / DN_BM, HIDDEN / DN_BN), 256, DN_SMEM>>>(out);
    (void)in_sizes; (void)n_in; (void)out_size;
}